// round 8
// baseline (speedup 1.0000x reference)
#include <cuda_runtime.h>
#include <cuda_bf16.h>
#include <math.h>
#include <stdint.h>

#define BB 2
#define NQ 2048
#define NK 2048
#define DD 1024
#define HH 16
#define HDIM 64

// Scratch (allocation-free: __device__ globals)
__device__ float g_Q[(size_t)BB * NQ * DD];
__device__ float g_K[(size_t)BB * NK * DD];
__device__ float g_V[(size_t)BB * NK * DD];
__device__ float g_O[(size_t)BB * NQ * DD];

// ---------------------------------------------------------------------------
// helpers
// ---------------------------------------------------------------------------
__device__ __forceinline__ uint32_t f2tf(float x) {
    uint32_t y;
    asm("cvt.rna.tf32.f32 %0, %1;" : "=r"(y) : "f"(x));
    return y;
}

__device__ __forceinline__ void mma8(float c[4], const uint32_t a[4], const uint32_t b[2]) {
    asm volatile(
        "mma.sync.aligned.m16n8k8.row.col.f32.tf32.tf32.f32 "
        "{%0,%1,%2,%3}, {%4,%5,%6,%7}, {%8,%9}, {%0,%1,%2,%3};\n"
        : "+f"(c[0]), "+f"(c[1]), "+f"(c[2]), "+f"(c[3])
        : "r"(a[0]), "r"(a[1]), "r"(a[2]), "r"(a[3]), "r"(b[0]), "r"(b[1]));
}

__device__ __forceinline__ void cpa16(uint32_t dst_smem, const void* src) {
    asm volatile("cp.async.cg.shared.global [%0], [%1], 16;\n" :: "r"(dst_smem), "l"(src));
}
__device__ __forceinline__ void cp_commit() {
    asm volatile("cp.async.commit_group;\n");
}
__device__ __forceinline__ void cp_wait0() { asm volatile("cp.async.wait_group 0;\n"); }
__device__ __forceinline__ void cp_wait1() { asm volatile("cp.async.wait_group 1;\n"); }
__device__ __forceinline__ void cp_wait2() { asm volatile("cp.async.wait_group 2;\n"); }

__device__ __forceinline__ void stcs2(float* p, float a, float b) {
    asm volatile("st.global.cs.v2.f32 [%0], {%1,%2};\n" :: "l"(p), "f"(a), "f"(b));
}

extern __shared__ char smraw[];

// ---------------------------------------------------------------------------
// Tensor-core GEMM + optional fused xpos-RoPE epilogue.
// 256x128 block tile, k-tile 32, cp.async double buffered. 256 threads,
// 8 warps (4x2), warp tile 64x64.
// ---------------------------------------------------------------------------
#define GBM 256
#define GBN 128
#define GBK 32
#define GPAD 36
#define GEMM_SMEM ((2 * GBM * GPAD + 2 * GBN * GPAD) * 4)

__global__ void __launch_bounds__(256, 1)
gemm_bias_rope_tc(const float* __restrict__ X, const float* __restrict__ W,
                  const float* __restrict__ bias, float* __restrict__ Y,
                  int M, int N, int K,
                  const float* __restrict__ freqs, float scale_base, float rsign,
                  int do_rope) {
    float* Xs = (float*)smraw;                 // [2][GBM][GPAD]
    float* Ws = Xs + 2 * GBM * GPAD;           // [2][GBN][GPAD]

    int tid = threadIdx.x;
    int warp = tid >> 5, lane = tid & 31;
    int g = lane >> 2, tig = lane & 3;
    int wm = warp >> 1, wn = warp & 1;         // 4 x 2 warps
    int row0 = blockIdx.y * GBM, col0 = blockIdx.x * GBN;

    uint32_t xsB = (uint32_t)__cvta_generic_to_shared(Xs);
    uint32_t wsB = (uint32_t)__cvta_generic_to_shared(Ws);

    float acc[4][8][4] = {};

#define GSTAGE(buf, kt)                                                          \
    do {                                                                         \
        _Pragma("unroll")                                                        \
        for (int i = 0; i < 8; i++) {                                            \
            int idx = tid + i * 256;                                             \
            int r = idx >> 3, c4 = (idx & 7) * 4;                                \
            cpa16(xsB + ((buf) * GBM * GPAD + r * GPAD + c4) * 4,                \
                  X + (size_t)(row0 + r) * K + (kt) + c4);                       \
        }                                                                        \
        _Pragma("unroll")                                                        \
        for (int i = 0; i < 4; i++) {                                            \
            int idx = tid + i * 256;                                             \
            int r = idx >> 3, c4 = (idx & 7) * 4;                                \
            cpa16(wsB + ((buf) * GBN * GPAD + r * GPAD + c4) * 4,                \
                  W + (size_t)(col0 + r) * K + (kt) + c4);                       \
        }                                                                        \
        cp_commit();                                                             \
    } while (0)

    GSTAGE(0, 0);
    int T = K / GBK;
    for (int t = 0; t < T; t++) {
        if (t + 1 < T) { GSTAGE((t + 1) & 1, (t + 1) * GBK); cp_wait1(); }
        else           { cp_wait0(); }
        __syncthreads();
        const float* Xb = Xs + (t & 1) * GBM * GPAD;
        const float* Wb = Ws + (t & 1) * GBN * GPAD;
#pragma unroll
        for (int ks = 0; ks < 4; ks++) {
            int k0 = ks * 8;
            uint32_t a[4][4], bf[8][2];
#pragma unroll
            for (int mi = 0; mi < 4; mi++) {
                int rb = wm * 64 + mi * 16 + g;
                a[mi][0] = f2tf(Xb[rb * GPAD + k0 + tig]);
                a[mi][1] = f2tf(Xb[(rb + 8) * GPAD + k0 + tig]);
                a[mi][2] = f2tf(Xb[rb * GPAD + k0 + tig + 4]);
                a[mi][3] = f2tf(Xb[(rb + 8) * GPAD + k0 + tig + 4]);
            }
#pragma unroll
            for (int ni = 0; ni < 8; ni++) {
                int cb = wn * 64 + ni * 8 + g;
                bf[ni][0] = f2tf(Wb[cb * GPAD + k0 + tig]);
                bf[ni][1] = f2tf(Wb[cb * GPAD + k0 + tig + 4]);
            }
#pragma unroll
            for (int mi = 0; mi < 4; mi++)
#pragma unroll
                for (int ni = 0; ni < 8; ni++)
                    mma8(acc[mi][ni], a[mi], bf[ni]);
        }
        __syncthreads();
    }
#undef GSTAGE

#pragma unroll
    for (int mi = 0; mi < 4; mi++) {
        int r = row0 + wm * 64 + mi * 16 + g;
#pragma unroll
        for (int ni = 0; ni < 8; ni++) {
            int c = col0 + wn * 64 + ni * 8 + tig * 2;
            float v0 = acc[mi][ni][0] + bias[c];
            float v1 = acc[mi][ni][1] + bias[c + 1];
            float v2 = acc[mi][ni][2] + bias[c];
            float v3 = acc[mi][ni][3] + bias[c + 1];
            if (do_rope) {
                int cd = c & (HDIM - 1);
                float f = freqs[cd >> 1];
                float sv = ((float)cd + 0.4f * (float)HDIM) / (1.4f * (float)HDIM);
                {
                    float n0 = (float)(r & (NQ - 1));
                    float sn, cs; sincosf(n0 * f, &sn, &cs);
                    float scale = powf(sv, (n0 - (float)(NQ / 2)) / scale_base * rsign);
                    float o0 = (v0 * cs - v1 * sn) * scale;
                    float o1 = (v1 * cs + v0 * sn) * scale;
                    v0 = o0; v1 = o1;
                }
                {
                    float n1 = (float)((r + 8) & (NQ - 1));
                    float sn, cs; sincosf(n1 * f, &sn, &cs);
                    float scale = powf(sv, (n1 - (float)(NQ / 2)) / scale_base * rsign);
                    float o2 = (v2 * cs - v3 * sn) * scale;
                    float o3 = (v3 * cs + v2 * sn) * scale;
                    v2 = o2; v3 = o3;
                }
            }
            *(float2*)(Y + (size_t)r * N + c) = make_float2(v0, v1);
            *(float2*)(Y + (size_t)(r + 8) * N + c) = make_float2(v2, v3);
        }
    }
}

// ---------------------------------------------------------------------------
// Fused attention, 512 threads / 16 warps (latency-bound fix: 2x warps).
// Pass 1: S = (0.125*Q)K^T, row sums of exp(S). Pass 2: recompute S
// (bit-identical), P = exp(S)*rinv -> gmem (streaming) + smem (tf32),
// O += P*V. S warp grid 4x4 (32x32 tiles); PV 8x2 (16x32 tiles).
// ---------------------------------------------------------------------------
#define APAD 68
#define PPAD 132
#define OQ_W 0
#define OK_W (128 * APAD)
#define OV_W (OK_W + 2 * 128 * APAD)
#define OP_W (OV_W + 128 * APAD)
#define OPART_W (OP_W + 128 * PPAD)
#define ORINV_W (OPART_W + 512)
#define ATTN_SMEM ((ORINV_W + 128) * 4)

__global__ void __launch_bounds__(512, 1)
attn_fused(const float* __restrict__ Q, const float* __restrict__ Kg,
           const float* __restrict__ Vg, float* __restrict__ attn,
           float* __restrict__ O) {
    uint32_t* smw = (uint32_t*)smraw;
    uint32_t* Qs = smw + OQ_W;              // [128][APAD] tf32
    float* Ks = (float*)(smw + OK_W);       // [2][128][APAD] raw f32
    float* Vs = (float*)(smw + OV_W);       // [128][APAD] raw f32
    uint32_t* Ps = smw + OP_W;              // [128][PPAD] tf32
    float* part = (float*)(smw + OPART_W);  // [4][128]
    float* rinv = (float*)(smw + ORINV_W);  // [128]

    int bh = blockIdx.y;
    int b = bh / HH, h = bh % HH;
    int q0 = blockIdx.x * 128;
    const float* Qb = Q + (size_t)b * NQ * DD + h * HDIM;
    const float* Kb = Kg + (size_t)b * NK * DD + h * HDIM;
    const float* Vb = Vg + (size_t)b * NK * DD + h * HDIM;
    float* outP = attn + (size_t)bh * NQ * NK;

    int tid = threadIdx.x;
    int warp = tid >> 5, lane = tid & 31;
    int g = lane >> 2, tig = lane & 3;
    int wm = warp >> 2, wn = warp & 3;      // 4x4 (S): 32x32 warp tiles
    int wm2 = warp >> 1, wn2 = warp & 1;    // 8x2 (PV): 16x32 warp tiles

    uint32_t ksB = (uint32_t)__cvta_generic_to_shared(Ks);
    uint32_t vsB = (uint32_t)__cvta_generic_to_shared(Vs);

#define KSTAGE(buf, kt)                                                          \
    do {                                                                         \
        _Pragma("unroll")                                                        \
        for (int i = 0; i < 4; i++) {                                            \
            int idx = tid + i * 512;                                             \
            int r = idx >> 4, c4 = (idx & 15) * 4;                               \
            cpa16(ksB + ((buf) * 128 * APAD + r * APAD + c4) * 4,                \
                  Kb + (size_t)((kt) * 128 + r) * DD + c4);                      \
        }                                                                        \
        cp_commit();                                                             \
    } while (0)

#define VSTAGE(kt)                                                               \
    do {                                                                         \
        _Pragma("unroll")                                                        \
        for (int i = 0; i < 4; i++) {                                            \
            int idx = tid + i * 512;                                             \
            int r = idx >> 4, c4 = (idx & 15) * 4;                               \
            cpa16(vsB + (r * APAD + c4) * 4,                                     \
                  Vb + (size_t)((kt) * 128 + r) * DD + c4);                      \
        }                                                                        \
        cp_commit();                                                             \
    } while (0)

    // Load Q tile once, pre-scaled by HD^-0.5 = 0.125.
#pragma unroll
    for (int i = 0; i < 4; i++) {
        int idx = tid + i * 512;
        int r = idx >> 4, c = (idx & 15) * 4;
        float4 v = *(const float4*)(Qb + (size_t)(q0 + r) * DD + c);
        uint32_t* p = Qs + r * APAD + c;
        p[0] = f2tf(v.x * 0.125f); p[1] = f2tf(v.y * 0.125f);
        p[2] = f2tf(v.z * 0.125f); p[3] = f2tf(v.w * 0.125f);
    }

    // ---------------- Pass 1: row sums of exp(S) ----------------
    float rs[4] = {};   // rows wm*32 + mi*16 + g (+8): index mi*2 + parity
    KSTAGE(0, 0);
    for (int kt = 0; kt < 16; kt++) {
        if (kt < 15) { KSTAGE((kt + 1) & 1, kt + 1); cp_wait1(); }
        else         { cp_wait0(); }
        __syncthreads();
        const float* Kbs = Ks + (kt & 1) * 128 * APAD;
        float acc[2][4][4] = {};
#pragma unroll
        for (int ks = 0; ks < 8; ks++) {
            int k0 = ks * 8;
            uint32_t a[2][4], bf[4][2];
#pragma unroll
            for (int mi = 0; mi < 2; mi++) {
                int rb = wm * 32 + mi * 16 + g;
                a[mi][0] = Qs[rb * APAD + k0 + tig];
                a[mi][1] = Qs[(rb + 8) * APAD + k0 + tig];
                a[mi][2] = Qs[rb * APAD + k0 + tig + 4];
                a[mi][3] = Qs[(rb + 8) * APAD + k0 + tig + 4];
            }
#pragma unroll
            for (int ni = 0; ni < 4; ni++) {
                int cb = wn * 32 + ni * 8 + g;
                bf[ni][0] = f2tf(Kbs[cb * APAD + k0 + tig]);
                bf[ni][1] = f2tf(Kbs[cb * APAD + k0 + tig + 4]);
            }
#pragma unroll
            for (int mi = 0; mi < 2; mi++)
#pragma unroll
                for (int ni = 0; ni < 4; ni++)
                    mma8(acc[mi][ni], a[mi], bf[ni]);
        }
#pragma unroll
        for (int mi = 0; mi < 2; mi++)
#pragma unroll
            for (int ni = 0; ni < 4; ni++) {
                rs[mi * 2 + 0] += __expf(acc[mi][ni][0]) + __expf(acc[mi][ni][1]);
                rs[mi * 2 + 1] += __expf(acc[mi][ni][2]) + __expf(acc[mi][ni][3]);
            }
        __syncthreads();
    }
    // Deterministic cross-warp row-sum reduction.
#pragma unroll
    for (int j = 0; j < 4; j++) {
        float v = rs[j];
        v += __shfl_xor_sync(0xffffffffu, v, 1);
        v += __shfl_xor_sync(0xffffffffu, v, 2);
        if (tig == 0)
            part[wn * 128 + wm * 32 + (j >> 1) * 16 + g + (j & 1) * 8] = v;
    }
    __syncthreads();
    if (tid < 128)
        rinv[tid] = 1.0f / (part[tid] + part[128 + tid] + part[256 + tid] + part[384 + tid]);
    __syncthreads();

    // ---------------- Pass 2: P out + P*V ----------------
    float acc_o[4][4] = {};
    KSTAGE(0, 0);
    for (int kt = 0; kt < 16; kt++) {
        if (kt < 15) KSTAGE((kt + 1) & 1, kt + 1);
        VSTAGE(kt);
        if (kt < 15) cp_wait2(); else cp_wait1();   // K(kt) ready
        __syncthreads();
        const float* Kbs = Ks + (kt & 1) * 128 * APAD;
        float acc[2][4][4] = {};
#pragma unroll
        for (int ks = 0; ks < 8; ks++) {
            int k0 = ks * 8;
            uint32_t a[2][4], bf[4][2];
#pragma unroll
            for (int mi = 0; mi < 2; mi++) {
                int rb = wm * 32 + mi * 16 + g;
                a[mi][0] = Qs[rb * APAD + k0 + tig];
                a[mi][1] = Qs[(rb + 8) * APAD + k0 + tig];
                a[mi][2] = Qs[rb * APAD + k0 + tig + 4];
                a[mi][3] = Qs[(rb + 8) * APAD + k0 + tig + 4];
            }
#pragma unroll
            for (int ni = 0; ni < 4; ni++) {
                int cb = wn * 32 + ni * 8 + g;
                bf[ni][0] = f2tf(Kbs[cb * APAD + k0 + tig]);
                bf[ni][1] = f2tf(Kbs[cb * APAD + k0 + tig + 4]);
            }
#pragma unroll
            for (int mi = 0; mi < 2; mi++)
#pragma unroll
                for (int ni = 0; ni < 4; ni++)
                    mma8(acc[mi][ni], a[mi], bf[ni]);
        }
        // Normalize, emit P to gmem (streaming) and smem (tf32).
#pragma unroll
        for (int mi = 0; mi < 2; mi++) {
            int rl = wm * 32 + mi * 16 + g;
            float ri0 = rinv[rl], ri1 = rinv[rl + 8];
#pragma unroll
            for (int ni = 0; ni < 4; ni++) {
                int cl = wn * 32 + ni * 8 + tig * 2;
                float p0 = __expf(acc[mi][ni][0]) * ri0;
                float p1 = __expf(acc[mi][ni][1]) * ri0;
                float p2 = __expf(acc[mi][ni][2]) * ri1;
                float p3 = __expf(acc[mi][ni][3]) * ri1;
                stcs2(outP + (size_t)(q0 + rl) * NK + kt * 128 + cl, p0, p1);
                stcs2(outP + (size_t)(q0 + rl + 8) * NK + kt * 128 + cl, p2, p3);
                uint32_t* pp = Ps + rl * PPAD + cl;
                pp[0] = f2tf(p0); pp[1] = f2tf(p1);
                uint32_t* pq = Ps + (rl + 8) * PPAD + cl;
                pq[0] = f2tf(p2); pq[1] = f2tf(p3);
            }
        }
        if (kt < 15) cp_wait1(); else cp_wait0();   // V(kt) ready
        __syncthreads();                            // Ps + Vs visible
        // O += P(128x128) * V(128x64): 8x2 warp grid, 16x32 tiles
#pragma unroll
        for (int ks = 0; ks < 16; ks++) {
            int k0 = ks * 8;
            uint32_t a[4], bf[4][2];
            int rb = wm2 * 16 + g;
            a[0] = Ps[rb * PPAD + k0 + tig];
            a[1] = Ps[(rb + 8) * PPAD + k0 + tig];
            a[2] = Ps[rb * PPAD + k0 + tig + 4];
            a[3] = Ps[(rb + 8) * PPAD + k0 + tig + 4];
#pragma unroll
            for (int ni = 0; ni < 4; ni++) {
                int nb = wn2 * 32 + ni * 8 + g;
                bf[ni][0] = f2tf(Vs[(k0 + tig) * APAD + nb]);
                bf[ni][1] = f2tf(Vs[(k0 + tig + 4) * APAD + nb]);
            }
#pragma unroll
            for (int ni = 0; ni < 4; ni++)
                mma8(acc_o[ni], a, bf[ni]);
        }
        __syncthreads();
    }
#undef KSTAGE
#undef VSTAGE

    // Write O
    {
        int r = q0 + wm2 * 16 + g;
#pragma unroll
        for (int ni = 0; ni < 4; ni++) {
            int c = wn2 * 32 + ni * 8 + tig * 2;
            float* o0 = O + ((size_t)b * NQ + r) * DD + h * HDIM + c;
            *(float2*)o0 = make_float2(acc_o[ni][0], acc_o[ni][1]);
            float* o1 = O + ((size_t)b * NQ + r + 8) * DD + h * HDIM + c;
            *(float2*)o1 = make_float2(acc_o[ni][2], acc_o[ni][3]);
        }
    }
}

// ---------------------------------------------------------------------------
extern "C" void kernel_launch(void* const* d_in, const int* in_sizes, int n_in,
                              void* d_out, int out_size) {
    const float* q_seq   = (const float*)d_in[0];
    const float* kv_seq  = (const float*)d_in[1];
    const float* Wq      = (const float*)d_in[2];
    const float* bq      = (const float*)d_in[3];
    const float* Wk      = (const float*)d_in[4];
    const float* bk      = (const float*)d_in[5];
    const float* Wv      = (const float*)d_in[6];
    const float* bv      = (const float*)d_in[7];
    const float* Wo      = (const float*)d_in[8];
    const float* bo      = (const float*)d_in[9];
    const float* freqs_q = (const float*)d_in[10];
    const float* freqs_kv= (const float*)d_in[11];

    float* out  = (float*)d_out;
    float* attn = out + (size_t)BB * NQ * DD;

    float *gQ, *gK, *gV, *gO;
    cudaGetSymbolAddress((void**)&gQ, g_Q);
    cudaGetSymbolAddress((void**)&gK, g_K);
    cudaGetSymbolAddress((void**)&gV, g_V);
    cudaGetSymbolAddress((void**)&gO, g_O);

    static int attr_done = 0;
    if (!attr_done) {
        cudaFuncSetAttribute(gemm_bias_rope_tc,
                             cudaFuncAttributeMaxDynamicSharedMemorySize, GEMM_SMEM);
        cudaFuncSetAttribute(attn_fused,
                             cudaFuncAttributeMaxDynamicSharedMemorySize, ATTN_SMEM);
        attr_done = 1;
    }

    dim3 gproj(DD / GBN, (BB * NQ) / GBM);   // 8 x 16 = 128 blocks

    gemm_bias_rope_tc<<<gproj, 256, GEMM_SMEM>>>(
        q_seq, Wq, bq, gQ, BB * NQ, DD, DD, freqs_q, (float)(2 * NQ), 1.0f, 1);
    gemm_bias_rope_tc<<<gproj, 256, GEMM_SMEM>>>(
        kv_seq, Wk, bk, gK, BB * NK, DD, DD, freqs_kv, (float)(2 * NK), -1.0f, 1);
    gemm_bias_rope_tc<<<gproj, 256, GEMM_SMEM>>>(
        kv_seq, Wv, bv, gV, BB * NK, DD, DD, nullptr, 1.0f, 0.0f, 0);

    attn_fused<<<dim3(NQ / 128, BB * HH), 512, ATTN_SMEM>>>(gQ, gK, gV, attn, gO);

    gemm_bias_rope_tc<<<gproj, 256, GEMM_SMEM>>>(
        gO, Wo, bo, out, BB * NQ, DD, DD, nullptr, 1.0f, 0.0f, 0);
}

// round 9
// speedup vs baseline: 1.1076x; 1.1076x over previous
#include <cuda_runtime.h>
#include <cuda_bf16.h>
#include <math.h>
#include <stdint.h>

#define BB 2
#define NQ 2048
#define NK 2048
#define DD 1024
#define HH 16
#define HDIM 64

// Scratch (allocation-free: __device__ globals)
__device__ float g_Q[(size_t)BB * NQ * DD];
__device__ float g_K[(size_t)BB * NK * DD];
__device__ float g_V[(size_t)BB * NK * DD];
__device__ float g_O[(size_t)BB * NQ * DD];

// ---------------------------------------------------------------------------
// helpers
// ---------------------------------------------------------------------------
__device__ __forceinline__ uint32_t f2tf(float x) {
    uint32_t y;
    asm("cvt.rna.tf32.f32 %0, %1;" : "=r"(y) : "f"(x));
    return y;
}

__device__ __forceinline__ void mma8(float c[4], const uint32_t a[4], const uint32_t b[2]) {
    asm volatile(
        "mma.sync.aligned.m16n8k8.row.col.f32.tf32.tf32.f32 "
        "{%0,%1,%2,%3}, {%4,%5,%6,%7}, {%8,%9}, {%0,%1,%2,%3};\n"
        : "+f"(c[0]), "+f"(c[1]), "+f"(c[2]), "+f"(c[3])
        : "r"(a[0]), "r"(a[1]), "r"(a[2]), "r"(a[3]), "r"(b[0]), "r"(b[1]));
}

__device__ __forceinline__ void cpa16(uint32_t dst_smem, const void* src) {
    asm volatile("cp.async.cg.shared.global [%0], [%1], 16;\n" :: "r"(dst_smem), "l"(src));
}
__device__ __forceinline__ void cp_commit() {
    asm volatile("cp.async.commit_group;\n");
}
__device__ __forceinline__ void cp_wait0() { asm volatile("cp.async.wait_group 0;\n"); }
__device__ __forceinline__ void cp_wait1() { asm volatile("cp.async.wait_group 1;\n"); }
__device__ __forceinline__ void cp_wait2() { asm volatile("cp.async.wait_group 2;\n"); }

__device__ __forceinline__ void stcs2(float* p, float a, float b) {
    asm volatile("st.global.cs.v2.f32 [%0], {%1,%2};\n" :: "l"(p), "f"(a), "f"(b));
}

extern __shared__ char smraw[];

// ---------------------------------------------------------------------------
// Tensor-core GEMM + optional fused xpos-RoPE epilogue. (unchanged from R7)
// 256x128 block tile, k-tile 32, cp.async double buffered. 256 threads,
// 8 warps (4x2), warp tile 64x64.
// ---------------------------------------------------------------------------
#define GBM 256
#define GBN 128
#define GBK 32
#define GPAD 36
#define GEMM_SMEM ((2 * GBM * GPAD + 2 * GBN * GPAD) * 4)

__global__ void __launch_bounds__(256, 1)
gemm_bias_rope_tc(const float* __restrict__ X, const float* __restrict__ W,
                  const float* __restrict__ bias, float* __restrict__ Y,
                  int M, int N, int K,
                  const float* __restrict__ freqs, float scale_base, float rsign,
                  int do_rope) {
    float* Xs = (float*)smraw;                 // [2][GBM][GPAD]
    float* Ws = Xs + 2 * GBM * GPAD;           // [2][GBN][GPAD]

    int tid = threadIdx.x;
    int warp = tid >> 5, lane = tid & 31;
    int g = lane >> 2, tig = lane & 3;
    int wm = warp >> 1, wn = warp & 1;         // 4 x 2 warps
    int row0 = blockIdx.y * GBM, col0 = blockIdx.x * GBN;

    uint32_t xsB = (uint32_t)__cvta_generic_to_shared(Xs);
    uint32_t wsB = (uint32_t)__cvta_generic_to_shared(Ws);

    float acc[4][8][4] = {};

#define GSTAGE(buf, kt)                                                          \
    do {                                                                         \
        _Pragma("unroll")                                                        \
        for (int i = 0; i < 8; i++) {                                            \
            int idx = tid + i * 256;                                             \
            int r = idx >> 3, c4 = (idx & 7) * 4;                                \
            cpa16(xsB + ((buf) * GBM * GPAD + r * GPAD + c4) * 4,                \
                  X + (size_t)(row0 + r) * K + (kt) + c4);                       \
        }                                                                        \
        _Pragma("unroll")                                                        \
        for (int i = 0; i < 4; i++) {                                            \
            int idx = tid + i * 256;                                             \
            int r = idx >> 3, c4 = (idx & 7) * 4;                                \
            cpa16(wsB + ((buf) * GBN * GPAD + r * GPAD + c4) * 4,                \
                  W + (size_t)(col0 + r) * K + (kt) + c4);                       \
        }                                                                        \
        cp_commit();                                                             \
    } while (0)

    GSTAGE(0, 0);
    int T = K / GBK;
    for (int t = 0; t < T; t++) {
        if (t + 1 < T) { GSTAGE((t + 1) & 1, (t + 1) * GBK); cp_wait1(); }
        else           { cp_wait0(); }
        __syncthreads();
        const float* Xb = Xs + (t & 1) * GBM * GPAD;
        const float* Wb = Ws + (t & 1) * GBN * GPAD;
#pragma unroll
        for (int ks = 0; ks < 4; ks++) {
            int k0 = ks * 8;
            uint32_t a[4][4], bf[8][2];
#pragma unroll
            for (int mi = 0; mi < 4; mi++) {
                int rb = wm * 64 + mi * 16 + g;
                a[mi][0] = f2tf(Xb[rb * GPAD + k0 + tig]);
                a[mi][1] = f2tf(Xb[(rb + 8) * GPAD + k0 + tig]);
                a[mi][2] = f2tf(Xb[rb * GPAD + k0 + tig + 4]);
                a[mi][3] = f2tf(Xb[(rb + 8) * GPAD + k0 + tig + 4]);
            }
#pragma unroll
            for (int ni = 0; ni < 8; ni++) {
                int cb = wn * 64 + ni * 8 + g;
                bf[ni][0] = f2tf(Wb[cb * GPAD + k0 + tig]);
                bf[ni][1] = f2tf(Wb[cb * GPAD + k0 + tig + 4]);
            }
#pragma unroll
            for (int mi = 0; mi < 4; mi++)
#pragma unroll
                for (int ni = 0; ni < 8; ni++)
                    mma8(acc[mi][ni], a[mi], bf[ni]);
        }
        __syncthreads();
    }
#undef GSTAGE

#pragma unroll
    for (int mi = 0; mi < 4; mi++) {
        int r = row0 + wm * 64 + mi * 16 + g;
#pragma unroll
        for (int ni = 0; ni < 8; ni++) {
            int c = col0 + wn * 64 + ni * 8 + tig * 2;
            float v0 = acc[mi][ni][0] + bias[c];
            float v1 = acc[mi][ni][1] + bias[c + 1];
            float v2 = acc[mi][ni][2] + bias[c];
            float v3 = acc[mi][ni][3] + bias[c + 1];
            if (do_rope) {
                int cd = c & (HDIM - 1);
                float f = freqs[cd >> 1];
                float sv = ((float)cd + 0.4f * (float)HDIM) / (1.4f * (float)HDIM);
                {
                    float n0 = (float)(r & (NQ - 1));
                    float sn, cs; sincosf(n0 * f, &sn, &cs);
                    float scale = powf(sv, (n0 - (float)(NQ / 2)) / scale_base * rsign);
                    float o0 = (v0 * cs - v1 * sn) * scale;
                    float o1 = (v1 * cs + v0 * sn) * scale;
                    v0 = o0; v1 = o1;
                }
                {
                    float n1 = (float)((r + 8) & (NQ - 1));
                    float sn, cs; sincosf(n1 * f, &sn, &cs);
                    float scale = powf(sv, (n1 - (float)(NQ / 2)) / scale_base * rsign);
                    float o2 = (v2 * cs - v3 * sn) * scale;
                    float o3 = (v3 * cs + v2 * sn) * scale;
                    v2 = o2; v3 = o3;
                }
            }
            *(float2*)(Y + (size_t)r * N + c) = make_float2(v0, v1);
            *(float2*)(Y + (size_t)(r + 8) * N + c) = make_float2(v2, v3);
        }
    }
}

// ---------------------------------------------------------------------------
// Fused attention, 256 threads (R7 grids), Q fragments RESIDENT in registers
// across both passes (kills A-fragment LDS + its latency chains).
// Pass 2 S-accumulators split into two ni-halves to bound register pressure.
// ---------------------------------------------------------------------------
#define APAD 68
#define PPAD 132
#define OQ_W 0
#define OK_W (128 * APAD)
#define OV_W (OK_W + 2 * 128 * APAD)
#define OP_W (OV_W + 128 * APAD)
#define OPART_W (OP_W + 128 * PPAD)
#define ORINV_W (OPART_W + 512)
#define ATTN_SMEM ((ORINV_W + 128) * 4)

__global__ void __launch_bounds__(256, 1)
attn_fused(const float* __restrict__ Q, const float* __restrict__ Kg,
           const float* __restrict__ Vg, float* __restrict__ attn,
           float* __restrict__ O) {
    uint32_t* smw = (uint32_t*)smraw;
    uint32_t* Qs = smw + OQ_W;              // [128][APAD] tf32 (staging only)
    float* Ks = (float*)(smw + OK_W);       // [2][128][APAD] raw f32
    float* Vs = (float*)(smw + OV_W);       // [128][APAD] raw f32
    uint32_t* Ps = smw + OP_W;              // [128][PPAD] tf32
    float* part = (float*)(smw + OPART_W);  // [4][128]
    float* rinv = (float*)(smw + ORINV_W);  // [128]

    int bh = blockIdx.y;
    int b = bh / HH, h = bh % HH;
    int q0 = blockIdx.x * 128;
    const float* Qb = Q + (size_t)b * NQ * DD + h * HDIM;
    const float* Kb = Kg + (size_t)b * NK * DD + h * HDIM;
    const float* Vb = Vg + (size_t)b * NK * DD + h * HDIM;
    float* outP = attn + (size_t)bh * NQ * NK;

    int tid = threadIdx.x;
    int warp = tid >> 5, lane = tid & 31;
    int g = lane >> 2, tig = lane & 3;
    int wm = warp >> 2, wn = warp & 3;      // 2x4 (S): 64x32 warp tiles
    int wm2 = warp >> 1, wn2 = warp & 1;    // 4x2 (PV): 32x32 warp tiles

    uint32_t ksB = (uint32_t)__cvta_generic_to_shared(Ks);
    uint32_t vsB = (uint32_t)__cvta_generic_to_shared(Vs);

#define KSTAGE(buf, kt)                                                          \
    do {                                                                         \
        _Pragma("unroll")                                                        \
        for (int i = 0; i < 8; i++) {                                            \
            int idx = tid + i * 256;                                             \
            int r = idx >> 4, c4 = (idx & 15) * 4;                               \
            cpa16(ksB + ((buf) * 128 * APAD + r * APAD + c4) * 4,                \
                  Kb + (size_t)((kt) * 128 + r) * DD + c4);                      \
        }                                                                        \
        cp_commit();                                                             \
    } while (0)

#define VSTAGE(kt)                                                               \
    do {                                                                         \
        _Pragma("unroll")                                                        \
        for (int i = 0; i < 8; i++) {                                            \
            int idx = tid + i * 256;                                             \
            int r = idx >> 4, c4 = (idx & 15) * 4;                               \
            cpa16(vsB + (r * APAD + c4) * 4,                                     \
                  Vb + (size_t)((kt) * 128 + r) * DD + c4);                      \
        }                                                                        \
        cp_commit();                                                             \
    } while (0)

    // Stage Q tile to smem (pre-scaled by HD^-0.5 = 0.125), then hoist the
    // per-warp fragment set into registers for the WHOLE kernel.
#pragma unroll
    for (int i = 0; i < 8; i++) {
        int idx = tid + i * 256;
        int r = idx >> 4, c = (idx & 15) * 4;
        float4 v = *(const float4*)(Qb + (size_t)(q0 + r) * DD + c);
        uint32_t* p = Qs + r * APAD + c;
        p[0] = f2tf(v.x * 0.125f); p[1] = f2tf(v.y * 0.125f);
        p[2] = f2tf(v.z * 0.125f); p[3] = f2tf(v.w * 0.125f);
    }
    __syncthreads();

    uint32_t qf[8][4][4];   // [ks][mi][frag] — Q resident, 128 regs
#pragma unroll
    for (int ks = 0; ks < 8; ks++) {
        int k0 = ks * 8;
#pragma unroll
        for (int mi = 0; mi < 4; mi++) {
            int rb = wm * 64 + mi * 16 + g;
            qf[ks][mi][0] = Qs[rb * APAD + k0 + tig];
            qf[ks][mi][1] = Qs[(rb + 8) * APAD + k0 + tig];
            qf[ks][mi][2] = Qs[rb * APAD + k0 + tig + 4];
            qf[ks][mi][3] = Qs[(rb + 8) * APAD + k0 + tig + 4];
        }
    }

    // ---------------- Pass 1: row sums of exp(S) ----------------
    float rs[8] = {};
    KSTAGE(0, 0);
    for (int kt = 0; kt < 16; kt++) {
        if (kt < 15) { KSTAGE((kt + 1) & 1, kt + 1); cp_wait1(); }
        else         { cp_wait0(); }
        __syncthreads();
        const float* Kbs = Ks + (kt & 1) * 128 * APAD;
#pragma unroll
        for (int half = 0; half < 2; half++) {
            float acc[4][2][4] = {};
#pragma unroll
            for (int ks = 0; ks < 8; ks++) {
                int k0 = ks * 8;
                uint32_t bf[2][2];
#pragma unroll
                for (int ni = 0; ni < 2; ni++) {
                    int cb = wn * 32 + (half * 2 + ni) * 8 + g;
                    bf[ni][0] = f2tf(Kbs[cb * APAD + k0 + tig]);
                    bf[ni][1] = f2tf(Kbs[cb * APAD + k0 + tig + 4]);
                }
#pragma unroll
                for (int mi = 0; mi < 4; mi++)
#pragma unroll
                    for (int ni = 0; ni < 2; ni++)
                        mma8(acc[mi][ni], qf[ks][mi], bf[ni]);
            }
#pragma unroll
            for (int mi = 0; mi < 4; mi++)
#pragma unroll
                for (int ni = 0; ni < 2; ni++) {
                    rs[mi * 2 + 0] += __expf(acc[mi][ni][0]) + __expf(acc[mi][ni][1]);
                    rs[mi * 2 + 1] += __expf(acc[mi][ni][2]) + __expf(acc[mi][ni][3]);
                }
        }
        __syncthreads();
    }
    // Deterministic cross-warp row-sum reduction.
#pragma unroll
    for (int j = 0; j < 8; j++) {
        float v = rs[j];
        v += __shfl_xor_sync(0xffffffffu, v, 1);
        v += __shfl_xor_sync(0xffffffffu, v, 2);
        if (tig == 0)
            part[wn * 128 + wm * 64 + (j >> 1) * 16 + g + (j & 1) * 8] = v;
    }
    __syncthreads();
    if (tid < 128)
        rinv[tid] = 1.0f / (part[tid] + part[128 + tid] + part[256 + tid] + part[384 + tid]);
    __syncthreads();

    // ---------------- Pass 2: P out + P*V ----------------
    float acc_o[2][4][4] = {};
    KSTAGE(0, 0);
    for (int kt = 0; kt < 16; kt++) {
        if (kt < 15) KSTAGE((kt + 1) & 1, kt + 1);
        VSTAGE(kt);
        if (kt < 15) cp_wait2(); else cp_wait1();   // K(kt) ready
        __syncthreads();
        const float* Kbs = Ks + (kt & 1) * 128 * APAD;
#pragma unroll
        for (int half = 0; half < 2; half++) {
            float acc[4][2][4] = {};
#pragma unroll
            for (int ks = 0; ks < 8; ks++) {
                int k0 = ks * 8;
                uint32_t bf[2][2];
#pragma unroll
                for (int ni = 0; ni < 2; ni++) {
                    int cb = wn * 32 + (half * 2 + ni) * 8 + g;
                    bf[ni][0] = f2tf(Kbs[cb * APAD + k0 + tig]);
                    bf[ni][1] = f2tf(Kbs[cb * APAD + k0 + tig + 4]);
                }
#pragma unroll
                for (int mi = 0; mi < 4; mi++)
#pragma unroll
                    for (int ni = 0; ni < 2; ni++)
                        mma8(acc[mi][ni], qf[ks][mi], bf[ni]);
            }
            // Normalize, emit P to gmem (streaming) and smem (tf32).
#pragma unroll
            for (int mi = 0; mi < 4; mi++) {
                int rl = wm * 64 + mi * 16 + g;
                float ri0 = rinv[rl], ri1 = rinv[rl + 8];
#pragma unroll
                for (int ni = 0; ni < 2; ni++) {
                    int cl = wn * 32 + (half * 2 + ni) * 8 + tig * 2;
                    float p0 = __expf(acc[mi][ni][0]) * ri0;
                    float p1 = __expf(acc[mi][ni][1]) * ri0;
                    float p2 = __expf(acc[mi][ni][2]) * ri1;
                    float p3 = __expf(acc[mi][ni][3]) * ri1;
                    stcs2(outP + (size_t)(q0 + rl) * NK + kt * 128 + cl, p0, p1);
                    stcs2(outP + (size_t)(q0 + rl + 8) * NK + kt * 128 + cl, p2, p3);
                    uint32_t* pp = Ps + rl * PPAD + cl;
                    pp[0] = f2tf(p0); pp[1] = f2tf(p1);
                    uint32_t* pq = Ps + (rl + 8) * PPAD + cl;
                    pq[0] = f2tf(p2); pq[1] = f2tf(p3);
                }
            }
        }
        if (kt < 15) cp_wait1(); else cp_wait0();   // V(kt) ready
        __syncthreads();                            // Ps + Vs visible
        // O += P(128x128) * V(128x64): 4x2 warp grid, 32x32 tiles
#pragma unroll
        for (int ks = 0; ks < 16; ks++) {
            int k0 = ks * 8;
            uint32_t a[2][4], bf[4][2];
#pragma unroll
            for (int mi = 0; mi < 2; mi++) {
                int rb = wm2 * 32 + mi * 16 + g;
                a[mi][0] = Ps[rb * PPAD + k0 + tig];
                a[mi][1] = Ps[(rb + 8) * PPAD + k0 + tig];
                a[mi][2] = Ps[rb * PPAD + k0 + tig + 4];
                a[mi][3] = Ps[(rb + 8) * PPAD + k0 + tig + 4];
            }
#pragma unroll
            for (int ni = 0; ni < 4; ni++) {
                int nb = wn2 * 32 + ni * 8 + g;
                bf[ni][0] = f2tf(Vs[(k0 + tig) * APAD + nb]);
                bf[ni][1] = f2tf(Vs[(k0 + tig + 4) * APAD + nb]);
            }
#pragma unroll
            for (int mi = 0; mi < 2; mi++)
#pragma unroll
                for (int ni = 0; ni < 4; ni++)
                    mma8(acc_o[mi][ni], a[mi], bf[ni]);
        }
        __syncthreads();
    }
#undef KSTAGE
#undef VSTAGE

    // Write O
#pragma unroll
    for (int mi = 0; mi < 2; mi++) {
        int r = q0 + wm2 * 32 + mi * 16 + g;
#pragma unroll
        for (int ni = 0; ni < 4; ni++) {
            int c = wn2 * 32 + ni * 8 + tig * 2;
            float* o0 = O + ((size_t)b * NQ + r) * DD + h * HDIM + c;
            *(float2*)o0 = make_float2(acc_o[mi][ni][0], acc_o[mi][ni][1]);
            float* o1 = O + ((size_t)b * NQ + r + 8) * DD + h * HDIM + c;
            *(float2*)o1 = make_float2(acc_o[mi][ni][2], acc_o[mi][ni][3]);
        }
    }
}

// ---------------------------------------------------------------------------
extern "C" void kernel_launch(void* const* d_in, const int* in_sizes, int n_in,
                              void* d_out, int out_size) {
    const float* q_seq   = (const float*)d_in[0];
    const float* kv_seq  = (const float*)d_in[1];
    const float* Wq      = (const float*)d_in[2];
    const float* bq      = (const float*)d_in[3];
    const float* Wk      = (const float*)d_in[4];
    const float* bk      = (const float*)d_in[5];
    const float* Wv      = (const float*)d_in[6];
    const float* bv      = (const float*)d_in[7];
    const float* Wo      = (const float*)d_in[8];
    const float* bo      = (const float*)d_in[9];
    const float* freqs_q = (const float*)d_in[10];
    const float* freqs_kv= (const float*)d_in[11];

    float* out  = (float*)d_out;
    float* attn = out + (size_t)BB * NQ * DD;

    float *gQ, *gK, *gV, *gO;
    cudaGetSymbolAddress((void**)&gQ, g_Q);
    cudaGetSymbolAddress((void**)&gK, g_K);
    cudaGetSymbolAddress((void**)&gV, g_V);
    cudaGetSymbolAddress((void**)&gO, g_O);

    static int attr_done = 0;
    if (!attr_done) {
        cudaFuncSetAttribute(gemm_bias_rope_tc,
                             cudaFuncAttributeMaxDynamicSharedMemorySize, GEMM_SMEM);
        cudaFuncSetAttribute(attn_fused,
                             cudaFuncAttributeMaxDynamicSharedMemorySize, ATTN_SMEM);
        attr_done = 1;
    }

    dim3 gproj(DD / GBN, (BB * NQ) / GBM);   // 8 x 16 = 128 blocks

    gemm_bias_rope_tc<<<gproj, 256, GEMM_SMEM>>>(
        q_seq, Wq, bq, gQ, BB * NQ, DD, DD, freqs_q, (float)(2 * NQ), 1.0f, 1);
    gemm_bias_rope_tc<<<gproj, 256, GEMM_SMEM>>>(
        kv_seq, Wk, bk, gK, BB * NK, DD, DD, freqs_kv, (float)(2 * NK), -1.0f, 1);
    gemm_bias_rope_tc<<<gproj, 256, GEMM_SMEM>>>(
        kv_seq, Wv, bv, gV, BB * NK, DD, DD, nullptr, 1.0f, 0.0f, 0);

    attn_fused<<<dim3(NQ / 128, BB * HH), 256, ATTN_SMEM>>>(gQ, gK, gV, attn, gO);

    gemm_bias_rope_tc<<<gproj, 256, GEMM_SMEM>>>(
        gO, Wo, bo, out, BB * NQ, DD, DD, nullptr, 1.0f, 0.0f, 0);
}